// round 4
// baseline (speedup 1.0000x reference)
#include <cuda_runtime.h>
#include <math.h>

#define CEn 128
#define TCn 1024
#define NWn 64
#define Wn  16
#define Tn  65536
#define Bn  4
#define EPSn 1e-5f
#define SLOPEn 0.01f

// Intermediate FiLM params: [B][4*NW][TC] = 4*256*1024 floats = 4 MB
__device__ float g_film[Bn * 4 * NWn * TCn];

// ---------------------------------------------------------------------------
// Kernel 1: TimeDistributedMLP  (Conv1x1 -> LN(ch) -> LeakyReLU) x3 -> Conv1x1
// One block per (t, b) column; 128 threads = 128 channels.
// ---------------------------------------------------------------------------
__global__ void mlp_kernel(const float* __restrict__ ce,
                           const float* __restrict__ w0, const float* __restrict__ b0,
                           const float* __restrict__ g0, const float* __restrict__ e0,
                           const float* __restrict__ w1, const float* __restrict__ b1,
                           const float* __restrict__ g1, const float* __restrict__ e1,
                           const float* __restrict__ w2, const float* __restrict__ b2,
                           const float* __restrict__ g2, const float* __restrict__ e2,
                           const float* __restrict__ w3, const float* __restrict__ b3)
{
    __shared__ float xs[CEn];
    __shared__ float red1[4], red2[4];

    const int t   = blockIdx.x;
    const int b   = blockIdx.y;
    const int tid = threadIdx.x;
    const int lane = tid & 31;
    const int wid  = tid >> 5;

    xs[tid] = ce[(b * CEn + tid) * TCn + t];
    __syncthreads();

    const float* Ws[3] = { w0, w1, w2 };
    const float* Bs[3] = { b0, b1, b2 };
    const float* Gs[3] = { g0, g1, g2 };
    const float* Es[3] = { e0, e1, e2 };

    for (int l = 0; l < 3; l++) {
        float acc = Bs[l][tid];
        const float4* wr = (const float4*)(Ws[l] + tid * CEn);
#pragma unroll 8
        for (int i = 0; i < CEn / 4; i++) {
            float4 wv = wr[i];
            acc += xs[4*i+0] * wv.x + xs[4*i+1] * wv.y
                 + xs[4*i+2] * wv.z + xs[4*i+3] * wv.w;
        }
        // block reduction of sum / sumsq over the 128 channel values
        float s1 = acc, s2 = acc * acc;
#pragma unroll
        for (int o = 16; o > 0; o >>= 1) {
            s1 += __shfl_xor_sync(0xffffffffu, s1, o);
            s2 += __shfl_xor_sync(0xffffffffu, s2, o);
        }
        if (lane == 0) { red1[wid] = s1; red2[wid] = s2; }
        __syncthreads();
        s1 = red1[0] + red1[1] + red1[2] + red1[3];
        s2 = red2[0] + red2[1] + red2[2] + red2[3];
        float mu  = s1 * (1.0f / CEn);
        float var = s2 * (1.0f / CEn) - mu * mu;
        float v = (acc - mu) * rsqrtf(var + EPSn);
        v = v * Gs[l][tid] + Es[l][tid];
        v = (v > 0.0f) ? v : SLOPEn * v;          // LeakyReLU
        __syncthreads();
        xs[tid] = v;
        __syncthreads();
    }

    // final CE -> 4*NW (256) layer
#pragma unroll
    for (int r = 0; r < 2; r++) {
        const int o = tid + r * CEn;
        float acc = b3[o];
        const float4* wr = (const float4*)(w3 + o * CEn);
#pragma unroll 8
        for (int i = 0; i < CEn / 4; i++) {
            float4 wv = wr[i];
            acc += xs[4*i+0] * wv.x + xs[4*i+1] * wv.y
                 + xs[4*i+2] * wv.z + xs[4*i+3] * wv.w;
        }
        g_film[(b * 4 * NWn + o) * TCn + t] = acc;
    }
}

// ---------------------------------------------------------------------------
// Kernel 2: FiLM + per-channel 1->16->16->1 sine MLP + FiLM-norm + x4 nearest
// upsample + 1x1 mixer, all fused. Each thread: 2 adjacent samples.
// ---------------------------------------------------------------------------
__device__ __forceinline__ float lerp_film(const float* __restrict__ f,
                                           int i0, int i1, float fr)
{
    float v0 = __ldg(f + i0);
    float v1 = __ldg(f + i1);
    return v0 + (v1 - v0) * fr;
}

__global__ void __launch_bounds__(128)
newt_kernel(const float* __restrict__ exciter,
            const float* __restrict__ iscale,
            const float* __restrict__ sw0, const float* __restrict__ sb0,
            const float* __restrict__ sw1, const float* __restrict__ sb1,
            const float* __restrict__ sw2, const float* __restrict__ sb2,
            const float* __restrict__ mixw, const float* __restrict__ mixb,
            float* __restrict__ out)
{
    const int tid = threadIdx.x;
    const int b   = blockIdx.y;
    const int t0  = blockIdx.x * 256;        // 128 threads * 2 samples
    const int ta  = t0 + 2 * tid;            // first sample of this thread

    const float* filmB = g_film + b * (4 * NWn * TCn);

    // linear-interp coordinates for both samples
    float pos = (ta + 0.5f) * (1.0f / 64.0f) - 0.5f;
    pos = fminf(fmaxf(pos, 0.0f), (float)(TCn - 1));
    const int i0a = (int)pos;
    const int i1a = min(i0a + 1, TCn - 1);
    const float fra = pos - (float)i0a;

    pos = (ta + 1.5f) * (1.0f / 64.0f) - 0.5f;
    pos = fminf(fmaxf(pos, 0.0f), (float)(TCn - 1));
    const int i0b = (int)pos;
    const int i1b = min(i0b + 1, TCn - 1);
    const float frb = pos - (float)i0b;

    float acc0 = 0.0f, acc1 = 0.0f;

    for (int c = 0; c < NWn; c++) {
        const float* fgi = filmB + (0 * NWn + c) * TCn;
        const float* fbi = filmB + (1 * NWn + c) * TCn;
        const float* fgn = filmB + (2 * NWn + c) * TCn;
        const float* fbn = filmB + (3 * NWn + c) * TCn;

        const float gia = lerp_film(fgi, i0a, i1a, fra);
        const float gib = lerp_film(fgi, i0b, i1b, frb);
        const float bia = lerp_film(fbi, i0a, i1a, fra);
        const float bib = lerp_film(fbi, i0b, i1b, frb);
        const float gna = lerp_film(fgn, i0a, i1a, fra);
        const float gnb = lerp_film(fgn, i0b, i1b, frb);
        const float bna = lerp_film(fbn, i0a, i1a, fra);
        const float bnb = lerp_film(fbn, i0b, i1b, frb);

        const float2 e = __ldg(((const float2*)(exciter + (b * NWn + c) * Tn)) + (t0 >> 1) + tid);
        const float isc = __ldg(iscale + c);

        const float x0 = isc * (gia * e.x + bia);
        const float x1 = isc * (gib * e.y + bib);

        // layer 0: 1 -> 16, sine
        float h0a[Wn], h0b[Wn];
        const float4* w0v = (const float4*)(sw0 + c * Wn);
        const float4* b0v = (const float4*)(sb0 + c * Wn);
#pragma unroll
        for (int j = 0; j < Wn / 4; j++) {
            float4 w = __ldg(w0v + j);
            float4 bb = __ldg(b0v + j);
            h0a[4*j+0] = __sinf(x0 * w.x + bb.x);
            h0a[4*j+1] = __sinf(x0 * w.y + bb.y);
            h0a[4*j+2] = __sinf(x0 * w.z + bb.z);
            h0a[4*j+3] = __sinf(x0 * w.w + bb.w);
            h0b[4*j+0] = __sinf(x1 * w.x + bb.x);
            h0b[4*j+1] = __sinf(x1 * w.y + bb.y);
            h0b[4*j+2] = __sinf(x1 * w.z + bb.z);
            h0b[4*j+3] = __sinf(x1 * w.w + bb.w);
        }

        // layer 1: 16 -> 16, sine
        float h1a[Wn], h1b[Wn];
        const float4* b1v = (const float4*)(sb1 + c * Wn);
#pragma unroll
        for (int o4i = 0; o4i < Wn / 4; o4i++) {
            float4 bv = __ldg(b1v + o4i);
            float bs[4] = { bv.x, bv.y, bv.z, bv.w };
#pragma unroll
            for (int oo = 0; oo < 4; oo++) {
                const int o = o4i * 4 + oo;
                float a0 = bs[oo];
                float a1 = bs[oo];
                const float4* wv = (const float4*)(sw1 + (c * Wn + o) * Wn);
#pragma unroll
                for (int i = 0; i < Wn / 4; i++) {
                    float4 w = __ldg(wv + i);
                    a0 += h0a[4*i+0] * w.x + h0a[4*i+1] * w.y
                        + h0a[4*i+2] * w.z + h0a[4*i+3] * w.w;
                    a1 += h0b[4*i+0] * w.x + h0b[4*i+1] * w.y
                        + h0b[4*i+2] * w.z + h0b[4*i+3] * w.w;
                }
                h1a[o] = __sinf(a0);
                h1b[o] = __sinf(a1);
            }
        }

        // layer 2: 16 -> 1, sine
        float a20 = __ldg(sb2 + c);
        float a21 = a20;
        const float4* w2v = (const float4*)(sw2 + c * Wn);
#pragma unroll
        for (int i = 0; i < Wn / 4; i++) {
            float4 w = __ldg(w2v + i);
            a20 += h1a[4*i+0] * w.x + h1a[4*i+1] * w.y
                 + h1a[4*i+2] * w.z + h1a[4*i+3] * w.w;
            a21 += h1b[4*i+0] * w.x + h1b[4*i+1] * w.y
                 + h1b[4*i+2] * w.z + h1b[4*i+3] * w.w;
        }
        const float y0 = __sinf(a20);
        const float y1 = __sinf(a21);

        const float mw = __ldg(mixw + c);
        acc0 += mw * (gna * y0 + bna);
        acc1 += mw * (gnb * y1 + bnb);
    }

    const float mb = __ldg(mixb);
    const float o0 = acc0 + mb;
    const float o1 = acc1 + mb;

    // nearest x4 upsample + write: out[b, 0, 4t .. 4t+3] as one float4 per sample
    float4* o4 = (float4*)out;
    o4[b * Tn + ta + 0] = make_float4(o0, o0, o0, o0);
    o4[b * Tn + ta + 1] = make_float4(o1, o1, o1, o1);
}

// ---------------------------------------------------------------------------
extern "C" void kernel_launch(void* const* d_in, const int* in_sizes, int n_in,
                              void* d_out, int out_size)
{
    const float* exciter = (const float*)d_in[0];
    const float* cemb    = (const float*)d_in[1];
    const float* mlp_w0  = (const float*)d_in[2];
    const float* mlp_b0  = (const float*)d_in[3];
    const float* ln0_g   = (const float*)d_in[4];
    const float* ln0_b   = (const float*)d_in[5];
    const float* mlp_w1  = (const float*)d_in[6];
    const float* mlp_b1  = (const float*)d_in[7];
    const float* ln1_g   = (const float*)d_in[8];
    const float* ln1_b   = (const float*)d_in[9];
    const float* mlp_w2  = (const float*)d_in[10];
    const float* mlp_b2  = (const float*)d_in[11];
    const float* ln2_g   = (const float*)d_in[12];
    const float* ln2_b   = (const float*)d_in[13];
    const float* mlp_w3  = (const float*)d_in[14];
    const float* mlp_b3  = (const float*)d_in[15];
    const float* iscale  = (const float*)d_in[16];
    const float* sf_w0   = (const float*)d_in[17];
    const float* sf_b0   = (const float*)d_in[18];
    const float* sf_w1   = (const float*)d_in[19];
    const float* sf_b1   = (const float*)d_in[20];
    const float* sf_w2   = (const float*)d_in[21];
    const float* sf_b2   = (const float*)d_in[22];
    const float* mix_w   = (const float*)d_in[23];
    const float* mix_b   = (const float*)d_in[24];
    float* out = (float*)d_out;

    dim3 g1(TCn, Bn);
    mlp_kernel<<<g1, CEn>>>(cemb,
                            mlp_w0, mlp_b0, ln0_g, ln0_b,
                            mlp_w1, mlp_b1, ln1_g, ln1_b,
                            mlp_w2, mlp_b2, ln2_g, ln2_b,
                            mlp_w3, mlp_b3);

    dim3 g2(Tn / 256, Bn);   // 128 threads * 2 samples = 256 samples/block
    newt_kernel<<<g2, 128>>>(exciter, iscale,
                             sf_w0, sf_b0, sf_w1, sf_b1, sf_w2, sf_b2,
                             mix_w, mix_b, out);
}

// round 5
// speedup vs baseline: 2.6278x; 2.6278x over previous
#include <cuda_runtime.h>
#include <math.h>

#define CEn 128
#define TCn 1024
#define NWn 64
#define Wn  16
#define Tn  65536
#define Bn  4
#define EPSn 1e-5f
#define SLOPEn 0.01f

// Intermediate FiLM params: [B][4*NW][TC] = 4*256*1024 floats = 4 MB
__device__ float g_film[Bn * 4 * NWn * TCn];

// ---------------------------------------------------------------------------
// Kernel 1: TimeDistributedMLP, tiled 16 time-columns per block.
// 128 threads = 128 output channels; each thread keeps acc[16].
// ---------------------------------------------------------------------------
#define TT 16
__global__ void __launch_bounds__(128)
mlp_kernel(const float* __restrict__ ce,
           const float* __restrict__ w0, const float* __restrict__ b0,
           const float* __restrict__ g0, const float* __restrict__ e0,
           const float* __restrict__ w1, const float* __restrict__ b1,
           const float* __restrict__ g1, const float* __restrict__ e1,
           const float* __restrict__ w2, const float* __restrict__ b2,
           const float* __restrict__ g2, const float* __restrict__ e2,
           const float* __restrict__ w3, const float* __restrict__ b3)
{
    __shared__ float xs[TT][CEn];        // [t][channel]
    __shared__ float red1[TT][4], red2[TT][4];

    const int t0  = blockIdx.x * TT;
    const int b   = blockIdx.y;
    const int tid = threadIdx.x;
    const int lane = tid & 31;
    const int wid  = tid >> 5;

#pragma unroll
    for (int tt = 0; tt < TT; tt++)
        xs[tt][tid] = ce[(b * CEn + tid) * TCn + t0 + tt];
    __syncthreads();

    const float* Ws[3] = { w0, w1, w2 };
    const float* Bs[3] = { b0, b1, b2 };
    const float* Gs[3] = { g0, g1, g2 };
    const float* Es[3] = { e0, e1, e2 };

    float acc[TT];

    for (int l = 0; l < 3; l++) {
        const float bb = Bs[l][tid];
#pragma unroll
        for (int tt = 0; tt < TT; tt++) acc[tt] = bb;

        const float4* wr = (const float4*)(Ws[l] + tid * CEn);
        for (int i = 0; i < CEn / 4; i++) {
            float4 wv = wr[i];
#pragma unroll
            for (int tt = 0; tt < TT; tt++) {
                const float4 xv = *(const float4*)&xs[tt][4 * i];
                acc[tt] += xv.x * wv.x + xv.y * wv.y + xv.z * wv.z + xv.w * wv.w;
            }
        }

        // LayerNorm over channels for each of the 16 columns
#pragma unroll
        for (int tt = 0; tt < TT; tt++) {
            float s1 = acc[tt], s2 = acc[tt] * acc[tt];
#pragma unroll
            for (int o = 16; o > 0; o >>= 1) {
                s1 += __shfl_xor_sync(0xffffffffu, s1, o);
                s2 += __shfl_xor_sync(0xffffffffu, s2, o);
            }
            if (lane == 0) { red1[tt][wid] = s1; red2[tt][wid] = s2; }
        }
        __syncthreads();

        const float gg = Gs[l][tid], ee = Es[l][tid];
#pragma unroll
        for (int tt = 0; tt < TT; tt++) {
            float s1 = red1[tt][0] + red1[tt][1] + red1[tt][2] + red1[tt][3];
            float s2 = red2[tt][0] + red2[tt][1] + red2[tt][2] + red2[tt][3];
            float mu  = s1 * (1.0f / CEn);
            float var = s2 * (1.0f / CEn) - mu * mu;
            float v = (acc[tt] - mu) * rsqrtf(var + EPSn);
            v = v * gg + ee;
            acc[tt] = (v > 0.0f) ? v : SLOPEn * v;
        }
        __syncthreads();
#pragma unroll
        for (int tt = 0; tt < TT; tt++) xs[tt][tid] = acc[tt];
        __syncthreads();
    }

    // final CE -> 4*NW (256) layer: each thread does 2 output rows
#pragma unroll
    for (int r = 0; r < 2; r++) {
        const int o = tid + r * CEn;
        const float bb = b3[o];
        float a2[TT];
#pragma unroll
        for (int tt = 0; tt < TT; tt++) a2[tt] = bb;
        const float4* wr = (const float4*)(w3 + o * CEn);
        for (int i = 0; i < CEn / 4; i++) {
            float4 wv = wr[i];
#pragma unroll
            for (int tt = 0; tt < TT; tt++) {
                const float4 xv = *(const float4*)&xs[tt][4 * i];
                a2[tt] += xv.x * wv.x + xv.y * wv.y + xv.z * wv.z + xv.w * wv.w;
            }
        }
#pragma unroll
        for (int tt = 0; tt < TT; tt++)
            g_film[(b * 4 * NWn + o) * TCn + t0 + tt] = a2[tt];
    }
}

// ---------------------------------------------------------------------------
// Kernel 2: fused waveshaper. 256 threads * 2 samples = 512 samples/block.
// All shaping weights + FiLM frame window staged in dynamic shared memory.
// ---------------------------------------------------------------------------
// shared layout (floats)
#define S_SW1   0                    // [64][16][16]
#define S_SW0   16384                // [64][16]
#define S_SB0   17408
#define S_SB1   18432
#define S_SW2   19456
#define S_SB2   20480                // [64]
#define S_ISC   20544
#define S_MIXW  20608
#define S_FILM  20672                // [4][64][10]
#define S_TOTAL (20672 + 4 * 64 * 10)   // 23232 floats = 92928 bytes
#define NFRAMES 10

__global__ void __launch_bounds__(256, 2)
newt_kernel(const float* __restrict__ exciter,
            const float* __restrict__ iscale,
            const float* __restrict__ sw0, const float* __restrict__ sb0,
            const float* __restrict__ sw1, const float* __restrict__ sb1,
            const float* __restrict__ sw2, const float* __restrict__ sb2,
            const float* __restrict__ mixw, const float* __restrict__ mixb,
            float* __restrict__ out)
{
    extern __shared__ float sm[];

    const int tid = threadIdx.x;
    const int b   = blockIdx.y;
    const int t0  = blockIdx.x * 512;        // 256 threads * 2 samples
    const int ta  = t0 + 2 * tid;

    // ---- stage weights ----
    for (int i = tid; i < 16384 / 4; i += 256)
        ((float4*)(sm + S_SW1))[i] = ((const float4*)sw1)[i];
    for (int i = tid; i < 1024 / 4; i += 256) {
        ((float4*)(sm + S_SW0))[i] = ((const float4*)sw0)[i];
        ((float4*)(sm + S_SB0))[i] = ((const float4*)sb0)[i];
        ((float4*)(sm + S_SB1))[i] = ((const float4*)sb1)[i];
        ((float4*)(sm + S_SW2))[i] = ((const float4*)sw2)[i];
    }
    if (tid < 64) {
        sm[S_SB2 + tid]  = sb2[tid];
        sm[S_ISC + tid]  = iscale[tid];
        sm[S_MIXW + tid] = mixw[tid];
    }

    // ---- stage film frame window ----
    // frames touched by samples [t0, t0+512): base .. base+9
    int base = (int)floorf((t0 + 0.5f) * (1.0f / 64.0f) - 0.5f);
    if (base < 0) base = 0;
    const float* filmB = g_film + b * (4 * NWn * TCn);
    for (int idx = tid; idx < 4 * NWn * NFRAMES; idx += 256) {
        const int p = idx / (NWn * NFRAMES);
        const int rem = idx - p * (NWn * NFRAMES);
        const int c = rem / NFRAMES;
        const int f = rem - c * NFRAMES;
        int fr = base + f; if (fr > TCn - 1) fr = TCn - 1;
        sm[S_FILM + (p * NWn + c) * NFRAMES + f] = filmB[(p * NWn + c) * TCn + fr];
    }
    __syncthreads();

    // linear-interp coordinates for both samples (local to frame window)
    float pos = (ta + 0.5f) * (1.0f / 64.0f) - 0.5f;
    pos = fminf(fmaxf(pos, 0.0f), (float)(TCn - 1));
    int i0a = (int)pos;
    int i1a = min(i0a + 1, TCn - 1);
    const float fra = pos - (float)i0a;
    i0a -= base; i1a -= base;

    pos = (ta + 1.5f) * (1.0f / 64.0f) - 0.5f;
    pos = fminf(fmaxf(pos, 0.0f), (float)(TCn - 1));
    int i0b = (int)pos;
    int i1b = min(i0b + 1, TCn - 1);
    const float frb = pos - (float)i0b;
    i0b -= base; i1b -= base;

    float acc0 = 0.0f, acc1 = 0.0f;

    for (int c = 0; c < NWn; c++) {
        const float* fgi = sm + S_FILM + (0 * NWn + c) * NFRAMES;
        const float* fbi = sm + S_FILM + (1 * NWn + c) * NFRAMES;
        const float* fgn = sm + S_FILM + (2 * NWn + c) * NFRAMES;
        const float* fbn = sm + S_FILM + (3 * NWn + c) * NFRAMES;

        const float gia = fgi[i0a] + (fgi[i1a] - fgi[i0a]) * fra;
        const float gib = fgi[i0b] + (fgi[i1b] - fgi[i0b]) * frb;
        const float bia = fbi[i0a] + (fbi[i1a] - fbi[i0a]) * fra;
        const float bib = fbi[i0b] + (fbi[i1b] - fbi[i0b]) * frb;
        const float gna = fgn[i0a] + (fgn[i1a] - fgn[i0a]) * fra;
        const float gnb = fgn[i0b] + (fgn[i1b] - fgn[i0b]) * frb;
        const float bna = fbn[i0a] + (fbn[i1a] - fbn[i0a]) * fra;
        const float bnb = fbn[i0b] + (fbn[i1b] - fbn[i0b]) * frb;

        const float2 e = __ldg(((const float2*)(exciter + (b * NWn + c) * Tn)) + (t0 >> 1) + tid);
        const float isc = sm[S_ISC + c];

        const float x0 = isc * (gia * e.x + bia);
        const float x1 = isc * (gib * e.y + bib);

        // layer 0: 1 -> 16, sine
        float h0a[Wn], h0b[Wn];
        const float4* w0v = (const float4*)(sm + S_SW0 + c * Wn);
        const float4* b0v = (const float4*)(sm + S_SB0 + c * Wn);
#pragma unroll
        for (int j = 0; j < Wn / 4; j++) {
            const float4 w  = w0v[j];
            const float4 bb = b0v[j];
            h0a[4*j+0] = __sinf(x0 * w.x + bb.x);
            h0a[4*j+1] = __sinf(x0 * w.y + bb.y);
            h0a[4*j+2] = __sinf(x0 * w.z + bb.z);
            h0a[4*j+3] = __sinf(x0 * w.w + bb.w);
            h0b[4*j+0] = __sinf(x1 * w.x + bb.x);
            h0b[4*j+1] = __sinf(x1 * w.y + bb.y);
            h0b[4*j+2] = __sinf(x1 * w.z + bb.z);
            h0b[4*j+3] = __sinf(x1 * w.w + bb.w);
        }

        // layer 1: 16 -> 16, sine
        float h1a[Wn], h1b[Wn];
        const float4* b1v = (const float4*)(sm + S_SB1 + c * Wn);
#pragma unroll
        for (int o4i = 0; o4i < Wn / 4; o4i++) {
            const float4 bv = b1v[o4i];
            const float bs[4] = { bv.x, bv.y, bv.z, bv.w };
#pragma unroll
            for (int oo = 0; oo < 4; oo++) {
                const int o = o4i * 4 + oo;
                float a0 = bs[oo];
                float a1 = bs[oo];
                const float4* wv = (const float4*)(sm + S_SW1 + (c * Wn + o) * Wn);
#pragma unroll
                for (int i = 0; i < Wn / 4; i++) {
                    const float4 w = wv[i];
                    a0 += h0a[4*i+0] * w.x + h0a[4*i+1] * w.y
                        + h0a[4*i+2] * w.z + h0a[4*i+3] * w.w;
                    a1 += h0b[4*i+0] * w.x + h0b[4*i+1] * w.y
                        + h0b[4*i+2] * w.z + h0b[4*i+3] * w.w;
                }
                h1a[o] = __sinf(a0);
                h1b[o] = __sinf(a1);
            }
        }

        // layer 2: 16 -> 1, sine
        float a20 = sm[S_SB2 + c];
        float a21 = a20;
        const float4* w2v = (const float4*)(sm + S_SW2 + c * Wn);
#pragma unroll
        for (int i = 0; i < Wn / 4; i++) {
            const float4 w = w2v[i];
            a20 += h1a[4*i+0] * w.x + h1a[4*i+1] * w.y
                 + h1a[4*i+2] * w.z + h1a[4*i+3] * w.w;
            a21 += h1b[4*i+0] * w.x + h1b[4*i+1] * w.y
                 + h1b[4*i+2] * w.z + h1b[4*i+3] * w.w;
        }
        const float y0 = __sinf(a20);
        const float y1 = __sinf(a21);

        const float mw = sm[S_MIXW + c];
        acc0 += mw * (gna * y0 + bna);
        acc1 += mw * (gnb * y1 + bnb);
    }

    const float mb = __ldg(mixb);
    const float o0 = acc0 + mb;
    const float o1 = acc1 + mb;

    // nearest x4 upsample + write
    float4* o4 = (float4*)out;
    o4[b * Tn + ta + 0] = make_float4(o0, o0, o0, o0);
    o4[b * Tn + ta + 1] = make_float4(o1, o1, o1, o1);
}

// ---------------------------------------------------------------------------
extern "C" void kernel_launch(void* const* d_in, const int* in_sizes, int n_in,
                              void* d_out, int out_size)
{
    const float* exciter = (const float*)d_in[0];
    const float* cemb    = (const float*)d_in[1];
    const float* mlp_w0  = (const float*)d_in[2];
    const float* mlp_b0  = (const float*)d_in[3];
    const float* ln0_g   = (const float*)d_in[4];
    const float* ln0_b   = (const float*)d_in[5];
    const float* mlp_w1  = (const float*)d_in[6];
    const float* mlp_b1  = (const float*)d_in[7];
    const float* ln1_g   = (const float*)d_in[8];
    const float* ln1_b   = (const float*)d_in[9];
    const float* mlp_w2  = (const float*)d_in[10];
    const float* mlp_b2  = (const float*)d_in[11];
    const float* ln2_g   = (const float*)d_in[12];
    const float* ln2_b   = (const float*)d_in[13];
    const float* mlp_w3  = (const float*)d_in[14];
    const float* mlp_b3  = (const float*)d_in[15];
    const float* iscale  = (const float*)d_in[16];
    const float* sf_w0   = (const float*)d_in[17];
    const float* sf_b0   = (const float*)d_in[18];
    const float* sf_w1   = (const float*)d_in[19];
    const float* sf_b1   = (const float*)d_in[20];
    const float* sf_w2   = (const float*)d_in[21];
    const float* sf_b2   = (const float*)d_in[22];
    const float* mix_w   = (const float*)d_in[23];
    const float* mix_b   = (const float*)d_in[24];
    float* out = (float*)d_out;

    dim3 g1(TCn / TT, Bn);
    mlp_kernel<<<g1, CEn>>>(cemb,
                            mlp_w0, mlp_b0, ln0_g, ln0_b,
                            mlp_w1, mlp_b1, ln1_g, ln1_b,
                            mlp_w2, mlp_b2, ln2_g, ln2_b,
                            mlp_w3, mlp_b3);

    const int smem_bytes = S_TOTAL * 4;
    cudaFuncSetAttribute(newt_kernel, cudaFuncAttributeMaxDynamicSharedMemorySize, smem_bytes);
    dim3 g2(Tn / 512, Bn);   // 256 threads * 2 samples = 512 samples/block
    newt_kernel<<<g2, 256, smem_bytes>>>(exciter, iscale,
                                         sf_w0, sf_b0, sf_w1, sf_b1, sf_w2, sf_b2,
                                         mix_w, mix_b, out);
}